// round 7
// baseline (speedup 1.0000x reference)
#include <cuda_runtime.h>

#define NN     8192
#define TC     128
#define NCH    (NN / TC)                 // 64
#define NTILES (NCH * (NCH + 1) / 2)     // 2080 upper-tri tiles
#define BLKSM  10
#define GRID   (148 * BLKSM)             // 1480 persistent blocks
#define LOG2E  1.4426950408889634f
#define LN2    0.6931471805599453

// Device-global scratch (allocation-free). The finalizing block resets
// everything after each run so graph replays are deterministic.
static __device__ double             g_sum  = 0.0;
static __device__ double             g_mse  = 0.0;
static __device__ unsigned long long g_cnt  = 0ull;
static __device__ unsigned int       g_done = 0u;
static __device__ unsigned int       g_tile = GRID;   // next tile to hand out

__device__ __forceinline__ float fast_ex2(float x) {
    float y; asm("ex2.approx.ftz.f32 %0, %1;" : "=f"(y) : "f"(x)); return y;
}
__device__ __forceinline__ float fast_lg2(float x) {
    float y; asm("lg2.approx.ftz.f32 %0, %1;" : "=f"(y) : "f"(x)); return y;
}

// tiles before row b (rows bi <= bj): b*NCH - b(b-1)/2
__device__ __forceinline__ int tri_off(int b) { return b * NCH - (b * (b - 1)) / 2; }

// Pair term, base-2 domain (pred pre-scaled by log2e; ln2 folded into finalize).
// ~10 SASS: FADD, FADD, LOP3, MUFU.EX2, FADD, MUFU.LG2, LOP3, FSETP, @p FFMA, @p FADD
__device__ __forceinline__ void pair_body(float ti, float pis, float tj, float pjs,
                                          float& sum, float& cnt) {
    float dt  = ti  - tj;
    float dps = pis - pjs;
    unsigned xb = __float_as_uint(dps) ^
                  ((__float_as_uint(dt) & 0x80000000u) ^ 0x80000000u);  // -sign(dt)*dps
    float u   = fast_ex2(__uint_as_float(xb));
    float l2  = fast_lg2(1.0f + u);
    float adt = fabsf(dt);
    if (adt > 0.1f) { sum = fmaf(adt, l2, sum); cnt += 1.0f; }
}

__global__ __launch_bounds__(TC, BLKSM)
void rk_persist(const float* __restrict__ pred, const float* __restrict__ targ,
                float* __restrict__ out) {
    __shared__ float2   s2[TC];          // (tj, pjs)
    __shared__ float    red[3][TC / 32];
    __shared__ unsigned s_next;

    const int t = threadIdx.x;

    // 4-way split accumulators: breaks the per-pair FFMA RAW chain that was
    // the real binder in R4/R5 (one serial 4-5cyc link per pair).
    float sum0 = 0.f, sum1 = 0.f, sum2 = 0.f, sum3 = 0.f;
    float cnt0 = 0.f, cnt1 = 0.f, cnt2 = 0.f, cnt3 = 0.f;
    float msq  = 0.f;

    unsigned tile = blockIdx.x;          // GRID < NTILES: every block starts with work
    while (tile < NTILES) {
        // decode linear tile id -> (bi, bj), bi <= bj
        const int k = (int)tile;
        float disc = (float)((2 * NCH + 1) * (2 * NCH + 1) - 8 * k);
        int bi = (int)(((float)(2 * NCH + 1) - sqrtf(disc)) * 0.5f);
        bi = min(max(bi, 0), NCH - 1);
        while (bi + 1 <= NCH - 1 && tri_off(bi + 1) <= k) ++bi;
        while (tri_off(bi) > k) --bi;
        const int bj = bi + (k - tri_off(bi));

        const int jg = bj * TC + t;
        const int ig = bi * TC + t;
        s2[t] = make_float2(targ[jg], pred[jg] * LOG2E);
        const float ti  = targ[ig];
        const float pi  = pred[ig];
        const float pis = pi * LOG2E;
        __syncthreads();

        if (bi == bj) {
            // Diagonal tile: j > i only; fold in this chunk's MSE (each i once).
            float dd = pi - ti;
            msq = fmaf(dd, dd, msq);
            int j = t + 1;
            for (; j < TC && (j & 3); ++j) {
                float2 v = s2[j];
                pair_body(ti, pis, v.x, v.y, sum0, cnt0);
            }
            for (; j < TC; j += 4) {
                float2 v0 = s2[j], v1 = s2[j + 1], v2 = s2[j + 2], v3 = s2[j + 3];
                pair_body(ti, pis, v0.x, v0.y, sum0, cnt0);
                pair_body(ti, pis, v1.x, v1.y, sum1, cnt1);
                pair_body(ti, pis, v2.x, v2.y, sum2, cnt2);
                pair_body(ti, pis, v3.x, v3.y, sum3, cnt3);
            }
        } else {
            // Off-diagonal: branch-free, 4 independent pairs per step
            // (2x LDS.128 broadcast), each feeding its own accumulator.
            const float4* s4 = reinterpret_cast<const float4*>(s2);
            #pragma unroll 8
            for (int q = 0; q < TC / 2; q += 2) {
                float4 a = s4[q];
                float4 b = s4[q + 1];
                pair_body(ti, pis, a.x, a.y, sum0, cnt0);
                pair_body(ti, pis, a.z, a.w, sum1, cnt1);
                pair_body(ti, pis, b.x, b.y, sum2, cnt2);
                pair_body(ti, pis, b.z, b.w, sum3, cnt3);
            }
        }

        // Grab next tile (greedy balance); sync also guards smem reuse.
        if (t == 0) s_next = atomicAdd(&g_tile, 1u);
        __syncthreads();
        tile = s_next;
    }

    // Per-block reduction (once per block, not per tile).
    float sum = (sum0 + sum1) + (sum2 + sum3);
    float fc  = (cnt0 + cnt1) + (cnt2 + cnt3);
    #pragma unroll
    for (int o = 16; o > 0; o >>= 1) {
        sum += __shfl_down_sync(0xffffffffu, sum, o);
        fc  += __shfl_down_sync(0xffffffffu, fc,  o);
        msq += __shfl_down_sync(0xffffffffu, msq, o);
    }
    const int lane = t & 31, warp = t >> 5;
    if (lane == 0) { red[0][warp] = sum; red[1][warp] = fc; red[2][warp] = msq; }
    __syncthreads();

    if (t == 0) {
        float bs = 0.f, bc = 0.f, bm = 0.f;
        #pragma unroll
        for (int w = 0; w < TC / 32; ++w) {
            bs += red[0][w]; bc += red[1][w]; bm += red[2][w];
        }
        atomicAdd(&g_sum, (double)bs);
        atomicAdd(&g_cnt, (unsigned long long)(bc + 0.5f));
        if (bm != 0.0f) atomicAdd(&g_mse, (double)bm);

        // Last block finalizes + resets for the next graph replay.
        __threadfence();
        unsigned prev = atomicAdd(&g_done, 1u);
        if (prev == GRID - 1) {
            double res = g_mse / (double)NN;            // regression loss
            unsigned long long c = g_cnt;
            if (c > 0) res += 3.0 * LN2 * g_sum / (double)c;
            out[0] = (float)res;
            g_sum = 0.0; g_mse = 0.0; g_cnt = 0ull; g_done = 0u; g_tile = GRID;
            __threadfence();
        }
    }
}

extern "C" void kernel_launch(void* const* d_in, const int* in_sizes, int n_in,
                              void* d_out, int out_size) {
    const float* pred = (const float*)d_in[0];
    const float* targ = (const float*)d_in[1];
    float* out = (float*)d_out;
    (void)in_sizes; (void)n_in; (void)out_size;

    rk_persist<<<GRID, TC>>>(pred, targ, out);
}